// round 13
// baseline (speedup 1.0000x reference)
#include <cuda_runtime.h>

#define DIM 2048
#define THETA 1e-18
#define REGEPS 1e-15

// first 50 primes (max 229)
__constant__ int c_primes[50] = {
    2,3,5,7,11,13,17,19,23,29,31,37,41,43,47,53,59,61,67,71,
    73,79,83,89,97,101,103,107,109,113,127,131,137,139,149,151,157,163,167,173,
    179,181,191,193,197,199,211,223,227,229};

#define ROWS_PER_CTA 4
#define HALO 8
#define TBL 20   // ROWS_PER_CTA + 2*HALO; band needs [base-6, base+9] ⊂ [base-8, base+12)

// R11 structure (all-thread zeroing + full __syncthreads + band overwrite),
// with the s-load hoisted above the zero stores and 4 rows/CTA (8 stores/thread).
__global__ void __launch_bounds__(256, 4)
fused_kernel(const float* __restrict__ s_real,
             const float* __restrict__ s_imag,
             float* __restrict__ out) {
    __shared__ double sO[TBL];   // Arnold off-1 (indexed by min index)
    __shared__ double sD[TBL];   // Re(n^{-s}) + prime diag corr
    __shared__ double sE[TBL];   // |s|*theta^2*exp(-0.01*m)

    const int base = blockIdx.x * ROWS_PER_CTA;
    const int t = threadIdx.x;
    const float PIf = 3.14159265358979323846f;

    // ---- issue the global load of s FIRST (hidden under the zero stores) ----
    float srf = 0.f, sif = 0.f;
    if (t < 96) {
        srf = __ldg(s_real);
        sif = __ldg(s_imag);
    }

    // ---- Phase B: zero this CTA's 4-row slab (4*512 = 2048 float4) ----
    {
        float4* o4 = (float4*)(out + (size_t)base * DIM);
        const float4 z = make_float4(0.f, 0.f, 0.f, 0.f);
        #pragma unroll
        for (int r = 0; r < 8; r++) o4[t + 256 * r] = z;
    }

    // ---- Phase A: tables via fp32 MUFU transcendentals (3 warps, 20 lanes live) ----
    if (t < 96) {
        int fam = t >> 5;
        int lm  = t & 31;
        if (lm < TBL) {
            int m  = base - HALO + lm;
            bool ok = (m >= 0 && m < DIM);
            if (fam == 0) {
                sO[lm] = (ok && m < DIM - 1)
                           ? (double)(THETA) * (double)sinf(PIf * (2.0f * (float)m + 1.0f) / (float)DIM)
                           : 0.0;
            } else if (fam == 1) {
                double dv = 0.0;
                if (ok) {
                    int n = m + 1;
                    float ln_n = logf((float)n);
                    bool isp = false;
                    #pragma unroll
                    for (int p = 0; p < 50; p++) isp |= (c_primes[p] == n);
                    float mag = expf(-srf * ln_n);   // Re(n^{-s}) = e^{-sr ln n} cos(si ln n)
                    float ph  = cosf(sif * ln_n);
                    dv = (double)mag * (double)ph;
                    if (isp) dv += THETA * (double)ln_n * 1.6449340668482264; // zeta(2)
                }
                sD[lm] = dv;
            } else {
                double ev = 0.0;
                if (ok) {
                    float abss = sqrtf(srf * srf + sif * sif);
                    ev = (double)abss * (THETA * THETA) * (double)expf(-0.01f * (float)m);
                }
                sE[lm] = ev;
            }
        }
    }

    __syncthreads();   // tables visible; zeros ordered before band overwrites

    // ---- Phase C: band elements (9 diagonals per row), fp64 accumulation ----
    int r = t >> 4;              // 0..15; only r<4 live
    int slot = t & 15;
    if (r < ROWS_PER_CTA && slot < 9) {
        int i = base + r;
        int j = i + slot - 4;
        if (j >= 0 && j < DIM) {
            auto aval = [&](int x, int y) -> double {
                if (y < 0 || y >= DIM) return 0.0;
                int dd = x - y; dd = dd < 0 ? -dd : dd;
                if (dd > 2) return 0.0;
                if (dd == 0) return 1.0;  // 1 + theta*cos rounds to exactly 1.0 (f64 too)
                if (dd == 1) return sO[(x < y ? x : y) - base + HALO];
                return THETA * THETA * 0.8187307530779818586699355086383;
            };
            double sre = 0.0;
            #pragma unroll
            for (int kk = -2; kk <= 2; kk++) {
                int k = i + kk;
                if (k < 0 || k >= DIM) continue;
                sre += aval(i, k) * sD[k - base + HALO] * aval(j, k);
            }
            int d = i - j;
            if (d == 0)                 sre += REGEPS;
            else if (d == 2 || d == -2) sre += sE[((i < j) ? i : j) - base + HALO];
            out[(size_t)i * DIM + j] = (float)sre;
        }
    }
}

// ---------------- fallback path (unexpected out_size; fp64 reference math) ----
__device__ double g_aDiag[DIM];
__device__ double g_aOff1[DIM];
__device__ double g_dDiag[DIM];
__device__ double g_exp2[DIM];

__global__ void precompute_kernel(const float* __restrict__ s_real,
                                  const float* __restrict__ s_imag) {
    int m = blockIdx.x * blockDim.x + threadIdx.x;
    if (m >= DIM) return;
    const double PI = 3.141592653589793238462643383279502884;
    double sr = (double)s_real[0], si = (double)s_imag[0];
    g_aDiag[m] = 1.0 + THETA * cos(2.0 * PI * (double)m / (double)DIM);
    g_aOff1[m] = (m < DIM - 1) ? THETA * sin(PI * (2.0 * (double)m + 1.0) / (double)DIM) : 0.0;
    int n = m + 1;
    double ln_n = log((double)n);
    bool isp = false;
    #pragma unroll
    for (int p = 0; p < 50; p++) isp |= (c_primes[p] == n);
    double dv = exp(-sr * ln_n) * cos(si * ln_n);
    if (isp) dv += THETA * ln_n * (PI * PI / 6.0);
    g_dDiag[m] = dv;
    g_exp2[m] = sqrt(sr * sr + si * si) * THETA * THETA * exp(-0.01 * (double)m);
}

__device__ __forceinline__ double AvalG(int x, int y) {
    if (y < 0 || y >= DIM) return 0.0;
    int d = x - y; d = d < 0 ? -d : d;
    if (d > 2) return 0.0;
    if (d == 0) return g_aDiag[x];
    if (d == 1) return g_aOff1[x < y ? x : y];
    return THETA * THETA * 0.8187307530779818586699355086383;
}

__global__ void fill_generic_f32(float* __restrict__ out, int n) {
    int idx = blockIdx.x * blockDim.x + threadIdx.x;
    if (idx >= n) return;
    int m = idx & (DIM * DIM - 1);
    int i = m >> 11, j = m & (DIM - 1);
    double sre = 0.0;
    #pragma unroll
    for (int kk = -2; kk <= 2; kk++) {
        int k = i + kk;
        if (k < 0 || k >= DIM) continue;
        sre += AvalG(i, k) * g_dDiag[k] * AvalG(j, k);
    }
    int d = i - j;
    if (d == 0) sre += REGEPS;
    else if (d == 2 || d == -2) sre += g_exp2[(i < j) ? i : j];
    out[idx] = (float)sre;
}

extern "C" void kernel_launch(void* const* d_in, const int* in_sizes, int n_in,
                              void* d_out, int out_size) {
    const float* s_real = (const float*)d_in[0];
    const float* s_imag = (const float*)((n_in >= 2) ? d_in[1] : d_in[0]);

    const int NTOT = DIM * DIM;
    if (out_size == NTOT) {
        fused_kernel<<<DIM / ROWS_PER_CTA, 256>>>(s_real, s_imag, (float*)d_out);
    } else {
        precompute_kernel<<<(DIM + 255) / 256, 256>>>(s_real, s_imag);
        fill_generic_f32<<<(out_size + 255) / 256, 256>>>((float*)d_out, out_size);
    }
}

// round 14
// speedup vs baseline: 1.4571x; 1.4571x over previous
#include <cuda_runtime.h>

#define DIM 2048
#define THETA 1e-18
#define REGEPS 1e-15

// Bitmask of primes among 1..2048 (bit n of word n>>5 set iff n prime).
// Covers all 50 needed primes (max 229) and beyond; indices are n = m+1 <= 2048.
__constant__ unsigned int c_pmask[64] = {
    0xa08a28acu, 0x28208a20u, 0x02088288u, 0x800228a2u,
    0x20a00a08u, 0x80282088u, 0x800800a2u, 0x08028228u,
    0x0a20a082u, 0x22880020u, 0x28020800u, 0x88208082u,
    0x02022020u, 0x08828028u, 0x8008a202u, 0x20880880u,
    0x20000a00u, 0x0a082008u, 0x82820802u, 0x00800a20u,
    0x0028208au, 0x20080822u, 0x20808020u, 0x02208088u,
    0x20080022u, 0x28a00a00u, 0x8a200080u, 0x008a2000u,
    0x00808800u, 0x02082202u, 0x80820880u, 0x28220020u,
    0x0a008200u, 0x20220888u, 0x28028800u, 0x80888088u,
    0x000a0220u, 0x20008020u, 0x80388000u, 0x20020028u,
    0x2808a008u, 0x20222800u, 0xa2000028u, 0x00888808u,
    0x00020200u, 0x02a08a08u, 0x00220028u, 0x80800a08u,
    0x0220a028u, 0x00880808u, 0x20020028u, 0x28000000u,
    0x88a00a08u, 0x02002020u, 0x80002088u, 0x00208880u,
    0x08200008u, 0x22008020u, 0x0a200280u, 0x00820820u,
    0x00020008u, 0x28228800u, 0x08008a00u, 0x20222000u};

#define ROWS_PER_CTA 8
#define HALO 8
#define TBL 24   // band needs [base-6, base+13] ⊂ [base-8, base+16)

// R11 structure (best measured): full-CTA zero + __syncthreads + band overwrite.
// Micro-cuts: s-load hoisted above the zero stores; prime test via bitmask.
__global__ void __launch_bounds__(256, 2)
fused_kernel(const float* __restrict__ s_real,
             const float* __restrict__ s_imag,
             float* __restrict__ out) {
    __shared__ double sO[TBL];   // Arnold off-1 (indexed by min index)
    __shared__ double sD[TBL];   // Re(n^{-s}) + prime diag corr
    __shared__ double sE[TBL];   // |s|*theta^2*exp(-0.01*m)

    const int base = blockIdx.x * ROWS_PER_CTA;
    const int t = threadIdx.x;
    const float PIf = 3.14159265358979323846f;

    // ---- issue the global loads of s FIRST; latency hidden under zero stores ----
    float srf = 0.f, sif = 0.f;
    if (t < 96) {
        srf = __ldg(s_real);
        sif = __ldg(s_imag);
    }

    // ---- Phase B: zero this CTA's 8-row slab (8*512 = 4096 float4) ----
    {
        float4* o4 = (float4*)(out + (size_t)base * DIM);
        const float4 z = make_float4(0.f, 0.f, 0.f, 0.f);
        #pragma unroll
        for (int r = 0; r < 16; r++) o4[t + 256 * r] = z;
    }

    // ---- Phase A: tables via fp32 MUFU transcendentals (3 warps, 24 lanes live) ----
    if (t < 96) {
        int fam = t >> 5;
        int lm  = t & 31;
        if (lm < TBL) {
            int m  = base - HALO + lm;
            bool ok = (m >= 0 && m < DIM);
            if (fam == 0) {
                sO[lm] = (ok && m < DIM - 1)
                           ? (double)(THETA) * (double)sinf(PIf * (2.0f * (float)m + 1.0f) / (float)DIM)
                           : 0.0;
            } else if (fam == 1) {
                double dv = 0.0;
                if (ok) {
                    int n = m + 1;
                    float ln_n = logf((float)n);
                    bool isp = (c_pmask[n >> 5] >> (n & 31)) & 1u;
                    float mag = expf(-srf * ln_n);   // Re(n^{-s}) = e^{-sr ln n} cos(si ln n)
                    float ph  = cosf(sif * ln_n);
                    dv = (double)mag * (double)ph;
                    if (isp) dv += THETA * (double)ln_n * 1.6449340668482264; // zeta(2)
                }
                sD[lm] = dv;
            } else {
                double ev = 0.0;
                if (ok) {
                    float abss = sqrtf(srf * srf + sif * sif);
                    ev = (double)abss * (THETA * THETA) * (double)expf(-0.01f * (float)m);
                }
                sE[lm] = ev;
            }
        }
    }

    __syncthreads();   // tables visible; zeros ordered before band overwrites

    // ---- Phase C: band elements (9 diagonals per row), fp64 accumulation ----
    int r = t >> 4;              // 0..15; r<8 live
    int slot = t & 15;
    if (r < ROWS_PER_CTA && slot < 9) {
        int i = base + r;
        int j = i + slot - 4;
        if (j >= 0 && j < DIM) {
            auto aval = [&](int x, int y) -> double {
                if (y < 0 || y >= DIM) return 0.0;
                int dd = x - y; dd = dd < 0 ? -dd : dd;
                if (dd > 2) return 0.0;
                if (dd == 0) return 1.0;  // 1 + theta*cos rounds to exactly 1.0 (f64 too)
                if (dd == 1) return sO[(x < y ? x : y) - base + HALO];
                return THETA * THETA * 0.8187307530779818586699355086383;
            };
            double sre = 0.0;
            #pragma unroll
            for (int kk = -2; kk <= 2; kk++) {
                int k = i + kk;
                if (k < 0 || k >= DIM) continue;
                sre += aval(i, k) * sD[k - base + HALO] * aval(j, k);
            }
            int d = i - j;
            if (d == 0)                 sre += REGEPS;
            else if (d == 2 || d == -2) sre += sE[((i < j) ? i : j) - base + HALO];
            out[(size_t)i * DIM + j] = (float)sre;
        }
    }
}

// ---------------- fallback path (unexpected out_size; fp64 reference math) ----
__device__ double g_aDiag[DIM];
__device__ double g_aOff1[DIM];
__device__ double g_dDiag[DIM];
__device__ double g_exp2[DIM];

__global__ void precompute_kernel(const float* __restrict__ s_real,
                                  const float* __restrict__ s_imag) {
    int m = blockIdx.x * blockDim.x + threadIdx.x;
    if (m >= DIM) return;
    const double PI = 3.141592653589793238462643383279502884;
    double sr = (double)s_real[0], si = (double)s_imag[0];
    g_aDiag[m] = 1.0 + THETA * cos(2.0 * PI * (double)m / (double)DIM);
    g_aOff1[m] = (m < DIM - 1) ? THETA * sin(PI * (2.0 * (double)m + 1.0) / (double)DIM) : 0.0;
    int n = m + 1;
    double ln_n = log((double)n);
    bool isp = (c_pmask[n >> 5] >> (n & 31)) & 1u;
    double dv = exp(-sr * ln_n) * cos(si * ln_n);
    if (isp) dv += THETA * ln_n * (PI * PI / 6.0);
    g_dDiag[m] = dv;
    g_exp2[m] = sqrt(sr * sr + si * si) * THETA * THETA * exp(-0.01 * (double)m);
}

__device__ __forceinline__ double AvalG(int x, int y) {
    if (y < 0 || y >= DIM) return 0.0;
    int d = x - y; d = d < 0 ? -d : d;
    if (d > 2) return 0.0;
    if (d == 0) return g_aDiag[x];
    if (d == 1) return g_aOff1[x < y ? x : y];
    return THETA * THETA * 0.8187307530779818586699355086383;
}

__global__ void fill_generic_f32(float* __restrict__ out, int n) {
    int idx = blockIdx.x * blockDim.x + threadIdx.x;
    if (idx >= n) return;
    int m = idx & (DIM * DIM - 1);
    int i = m >> 11, j = m & (DIM - 1);
    double sre = 0.0;
    #pragma unroll
    for (int kk = -2; kk <= 2; kk++) {
        int k = i + kk;
        if (k < 0 || k >= DIM) continue;
        sre += AvalG(i, k) * g_dDiag[k] * AvalG(j, k);
    }
    int d = i - j;
    if (d == 0) sre += REGEPS;
    else if (d == 2 || d == -2) sre += g_exp2[(i < j) ? i : j];
    out[idx] = (float)sre;
}

extern "C" void kernel_launch(void* const* d_in, const int* in_sizes, int n_in,
                              void* d_out, int out_size) {
    const float* s_real = (const float*)d_in[0];
    const float* s_imag = (const float*)((n_in >= 2) ? d_in[1] : d_in[0]);

    const int NTOT = DIM * DIM;
    if (out_size == NTOT) {
        fused_kernel<<<DIM / ROWS_PER_CTA, 256>>>(s_real, s_imag, (float*)d_out);
    } else {
        precompute_kernel<<<(DIM + 255) / 256, 256>>>(s_real, s_imag);
        fill_generic_f32<<<(out_size + 255) / 256, 256>>>((float*)d_out, out_size);
    }
}

// round 16
// speedup vs baseline: 1.4624x; 1.0036x over previous
#include <cuda_runtime.h>

#define DIM 2048
#define THETA 1e-18
#define REGEPS 1e-15

// Bitmask of primes among 1..2048 (bit n of word n>>5 set iff n prime).
__constant__ unsigned int c_pmask[64] = {
    0xa08a28acu, 0x28208a20u, 0x02088288u, 0x800228a2u,
    0x20a00a08u, 0x80282088u, 0x800800a2u, 0x08028228u,
    0x0a20a082u, 0x22880020u, 0x28020800u, 0x88208082u,
    0x02022020u, 0x08828028u, 0x8008a202u, 0x20880880u,
    0x20000a00u, 0x0a082008u, 0x82820802u, 0x00800a20u,
    0x0028208au, 0x20080822u, 0x20808020u, 0x02208088u,
    0x20080022u, 0x28a00a00u, 0x8a200080u, 0x008a2000u,
    0x00808800u, 0x02082202u, 0x80820880u, 0x28220020u,
    0x0a008200u, 0x20220888u, 0x28028800u, 0x80888088u,
    0x000a0220u, 0x20008020u, 0x80388000u, 0x20020028u,
    0x2808a008u, 0x20222800u, 0xa2000028u, 0x00888808u,
    0x00020200u, 0x02a08a08u, 0x00220028u, 0x80800a08u,
    0x0220a028u, 0x00880808u, 0x20020028u, 0x28000000u,
    0x88a00a08u, 0x02002020u, 0x80002088u, 0x00208880u,
    0x08200008u, 0x22008020u, 0x0a200280u, 0x00820820u,
    0x00020008u, 0x28228800u, 0x08008a00u, 0x20222000u};

#define ROWS_PER_CTA 16
#define HALO 8
#define TBL 32   // band needs [base-6, base+21] ⊂ [base-8, base+24)

// Best-measured structure (R10: grid 128 x 16 rows) + hoisted s-load + bitmask
// prime test + fp32 phase C (short FFMA tail instead of ~250-cyc DFMA chain).
__global__ void __launch_bounds__(256, 1)
fused_kernel(const float* __restrict__ s_real,
             const float* __restrict__ s_imag,
             float* __restrict__ out) {
    __shared__ float sO[TBL];   // Arnold off-1 (theta*sin; ~1e-18, fp32 normal)
    __shared__ float sD[TBL];   // Re(n^{-s}) + prime diag corr
    __shared__ float sE[TBL];   // |s|*theta^2*exp(-0.01*m)

    const int base = blockIdx.x * ROWS_PER_CTA;
    const int t = threadIdx.x;
    const float PIf = 3.14159265358979323846f;

    // ---- issue the global loads of s FIRST; latency hidden under zero stores ----
    float srf = 0.f, sif = 0.f;
    if (t < 96) {
        srf = __ldg(s_real);
        sif = __ldg(s_imag);
    }

    // ---- Phase B: zero this CTA's 16-row slab (16*512 = 8192 float4) ----
    {
        float4* o4 = (float4*)(out + (size_t)base * DIM);
        const float4 z = make_float4(0.f, 0.f, 0.f, 0.f);
        #pragma unroll
        for (int r = 0; r < 32; r++) o4[t + 256 * r] = z;
    }

    // ---- Phase A: tables via fp32 MUFU transcendentals (3 warps, 32 lanes) ----
    if (t < 96) {
        int fam = t >> 5;
        int lm  = t & 31;
        int m   = base - HALO + lm;
        bool ok = (m >= 0 && m < DIM);
        if (fam == 0) {
            sO[lm] = (ok && m < DIM - 1)
                       ? (float)(THETA) * sinf(PIf * (2.0f * (float)m + 1.0f) / (float)DIM)
                       : 0.0f;
        } else if (fam == 1) {
            float dv = 0.0f;
            if (ok) {
                int n = m + 1;
                float ln_n = logf((float)n);
                bool isp = (c_pmask[n >> 5] >> (n & 31)) & 1u;
                dv = expf(-srf * ln_n) * cosf(sif * ln_n);   // Re(n^{-s})
                if (isp) dv += (float)(THETA) * ln_n * 1.6449341f; // zeta(2)
            }
            sD[lm] = dv;
        } else {
            float ev = 0.0f;
            if (ok) {
                float abss = sqrtf(srf * srf + sif * sif);
                ev = abss * (float)(THETA * THETA) * expf(-0.01f * (float)m);
            }
            sE[lm] = ev;
        }
    }

    __syncthreads();   // tables visible; zeros ordered before band overwrites

    // ---- Phase C: band elements (9 diagonals per row), fp32 FFMA chain ----
    int r = t >> 4;
    int slot = t & 15;
    if (slot < 9) {
        int i = base + r;
        int j = i + slot - 4;
        if (j >= 0 && j < DIM) {
            auto aval = [&](int x, int y) -> float {
                if (y < 0 || y >= DIM) return 0.0f;
                int dd = x - y; dd = dd < 0 ? -dd : dd;
                if (dd > 2) return 0.0f;
                if (dd == 0) return 1.0f;  // 1 + theta*cos == 1.0 exactly (f64 too)
                if (dd == 1) return sO[(x < y ? x : y) - base + HALO];
                return (float)(THETA * THETA * 0.8187307530779818);
            };
            float sre = 0.0f;
            #pragma unroll
            for (int kk = -2; kk <= 2; kk++) {
                int k = i + kk;
                if (k < 0 || k >= DIM) continue;
                sre += aval(i, k) * sD[k - base + HALO] * aval(j, k);
            }
            int d = i - j;
            if (d == 0)                 sre += (float)REGEPS;
            else if (d == 2 || d == -2) sre += sE[((i < j) ? i : j) - base + HALO];
            out[(size_t)i * DIM + j] = sre;
        }
    }
}

// ---------------- fallback path (unexpected out_size; fp64 reference math) ----
__device__ double g_aDiag[DIM];
__device__ double g_aOff1[DIM];
__device__ double g_dDiag[DIM];
__device__ double g_exp2[DIM];

__global__ void precompute_kernel(const float* __restrict__ s_real,
                                  const float* __restrict__ s_imag) {
    int m = blockIdx.x * blockDim.x + threadIdx.x;
    if (m >= DIM) return;
    const double PI = 3.141592653589793238462643383279502884;
    double sr = (double)s_real[0], si = (double)s_imag[0];
    g_aDiag[m] = 1.0 + THETA * cos(2.0 * PI * (double)m / (double)DIM);
    g_aOff1[m] = (m < DIM - 1) ? THETA * sin(PI * (2.0 * (double)m + 1.0) / (double)DIM) : 0.0;
    int n = m + 1;
    double ln_n = log((double)n);
    bool isp = (c_pmask[n >> 5] >> (n & 31)) & 1u;
    double dv = exp(-sr * ln_n) * cos(si * ln_n);
    if (isp) dv += THETA * ln_n * (PI * PI / 6.0);
    g_dDiag[m] = dv;
    g_exp2[m] = sqrt(sr * sr + si * si) * THETA * THETA * exp(-0.01 * (double)m);
}

__device__ __forceinline__ double AvalG(int x, int y) {
    if (y < 0 || y >= DIM) return 0.0;
    int d = x - y; d = d < 0 ? -d : d;
    if (d > 2) return 0.0;
    if (d == 0) return g_aDiag[x];
    if (d == 1) return g_aOff1[x < y ? x : y];
    return THETA * THETA * 0.8187307530779818586699355086383;
}

__global__ void fill_generic_f32(float* __restrict__ out, int n) {
    int idx = blockIdx.x * blockDim.x + threadIdx.x;
    if (idx >= n) return;
    int m = idx & (DIM * DIM - 1);
    int i = m >> 11, j = m & (DIM - 1);
    double sre = 0.0;
    #pragma unroll
    for (int kk = -2; kk <= 2; kk++) {
        int k = i + kk;
        if (k < 0 || k >= DIM) continue;
        sre += AvalG(i, k) * g_dDiag[k] * AvalG(j, k);
    }
    int d = i - j;
    if (d == 0) sre += REGEPS;
    else if (d == 2 || d == -2) sre += g_exp2[(i < j) ? i : j];
    out[idx] = (float)sre;
}

extern "C" void kernel_launch(void* const* d_in, const int* in_sizes, int n_in,
                              void* d_out, int out_size) {
    const float* s_real = (const float*)d_in[0];
    const float* s_imag = (const float*)((n_in >= 2) ? d_in[1] : d_in[0]);

    const int NTOT = DIM * DIM;
    if (out_size == NTOT) {
        fused_kernel<<<DIM / ROWS_PER_CTA, 256>>>(s_real, s_imag, (float*)d_out);
    } else {
        precompute_kernel<<<(DIM + 255) / 256, 256>>>(s_real, s_imag);
        fill_generic_f32<<<(out_size + 255) / 256, 256>>>((float*)d_out, out_size);
    }
}

// round 17
// speedup vs baseline: 1.5055x; 1.0295x over previous
#include <cuda_runtime.h>

#define DIM 2048
#define THETA 1e-18
#define REGEPS 1e-15

// Bitmask of primes among 1..2048 (bit n of word n>>5 set iff n prime).
__constant__ unsigned int c_pmask[64] = {
    0xa08a28acu, 0x28208a20u, 0x02088288u, 0x800228a2u,
    0x20a00a08u, 0x80282088u, 0x800800a2u, 0x08028228u,
    0x0a20a082u, 0x22880020u, 0x28020800u, 0x88208082u,
    0x02022020u, 0x08828028u, 0x8008a202u, 0x20880880u,
    0x20000a00u, 0x0a082008u, 0x82820802u, 0x00800a20u,
    0x0028208au, 0x20080822u, 0x20808020u, 0x02208088u,
    0x20080022u, 0x28a00a00u, 0x8a200080u, 0x008a2000u,
    0x00808800u, 0x02082202u, 0x80820880u, 0x28220020u,
    0x0a008200u, 0x20220888u, 0x28028800u, 0x80888088u,
    0x000a0220u, 0x20008020u, 0x80388000u, 0x20020028u,
    0x2808a008u, 0x20222800u, 0xa2000028u, 0x00888808u,
    0x00020200u, 0x02a08a08u, 0x00220028u, 0x80800a08u,
    0x0220a028u, 0x00880808u, 0x20020028u, 0x28000000u,
    0x88a00a08u, 0x02002020u, 0x80002088u, 0x00208880u,
    0x08200008u, 0x22008020u, 0x0a200280u, 0x00820820u,
    0x00020008u, 0x28228800u, 0x08008a00u, 0x20222000u};

#define ROWS_PER_CTA 16
#define HALO 8
#define TBL 32   // band needs [base-6, base+21] ⊂ [base-8, base+24)
#define NTHREADS 512

// 128 CTAs (best measured) x 512 threads: 2x resident warps per SM pushing
// STG.128 streams; 16 stores/thread. Tables/band identical to R16.
__global__ void __launch_bounds__(NTHREADS, 1)
fused_kernel(const float* __restrict__ s_real,
             const float* __restrict__ s_imag,
             float* __restrict__ out) {
    __shared__ float sO[TBL];   // Arnold off-1 (theta*sin; fp32 normal)
    __shared__ float sD[TBL];   // Re(n^{-s}) + prime diag corr
    __shared__ float sE[TBL];   // |s|*theta^2*exp(-0.01*m)

    const int base = blockIdx.x * ROWS_PER_CTA;
    const int t = threadIdx.x;
    const float PIf = 3.14159265358979323846f;

    // ---- issue the global loads of s FIRST; latency hidden under zero stores ----
    float srf = 0.f, sif = 0.f;
    if (t < 96) {
        srf = __ldg(s_real);
        sif = __ldg(s_imag);
    }

    // ---- Phase B: zero this CTA's 16-row slab (8192 float4, 16 per thread) ----
    {
        float4* o4 = (float4*)(out + (size_t)base * DIM);
        const float4 z = make_float4(0.f, 0.f, 0.f, 0.f);
        #pragma unroll
        for (int r = 0; r < 16; r++) o4[t + NTHREADS * r] = z;
    }

    // ---- Phase A: tables via fp32 MUFU transcendentals (3 warps, 32 lanes) ----
    if (t < 96) {
        int fam = t >> 5;
        int lm  = t & 31;
        int m   = base - HALO + lm;
        bool ok = (m >= 0 && m < DIM);
        if (fam == 0) {
            sO[lm] = (ok && m < DIM - 1)
                       ? (float)(THETA) * sinf(PIf * (2.0f * (float)m + 1.0f) / (float)DIM)
                       : 0.0f;
        } else if (fam == 1) {
            float dv = 0.0f;
            if (ok) {
                int n = m + 1;
                float ln_n = logf((float)n);
                bool isp = (c_pmask[n >> 5] >> (n & 31)) & 1u;
                dv = expf(-srf * ln_n) * cosf(sif * ln_n);   // Re(n^{-s})
                if (isp) dv += (float)(THETA) * ln_n * 1.6449341f; // zeta(2)
            }
            sD[lm] = dv;
        } else {
            float ev = 0.0f;
            if (ok) {
                float abss = sqrtf(srf * srf + sif * sif);
                ev = abss * (float)(THETA * THETA) * expf(-0.01f * (float)m);
            }
            sE[lm] = ev;
        }
    }

    __syncthreads();   // tables visible; zeros ordered before band overwrites

    // ---- Phase C: band elements (9 diagonals per row), fp32 FFMA chain ----
    int r = t >> 4;              // 0..31; r<16 live
    int slot = t & 15;
    if (r < ROWS_PER_CTA && slot < 9) {
        int i = base + r;
        int j = i + slot - 4;
        if (j >= 0 && j < DIM) {
            auto aval = [&](int x, int y) -> float {
                if (y < 0 || y >= DIM) return 0.0f;
                int dd = x - y; dd = dd < 0 ? -dd : dd;
                if (dd > 2) return 0.0f;
                if (dd == 0) return 1.0f;  // 1 + theta*cos == 1.0 exactly (f64 too)
                if (dd == 1) return sO[(x < y ? x : y) - base + HALO];
                return (float)(THETA * THETA * 0.8187307530779818);
            };
            float sre = 0.0f;
            #pragma unroll
            for (int kk = -2; kk <= 2; kk++) {
                int k = i + kk;
                if (k < 0 || k >= DIM) continue;
                sre += aval(i, k) * sD[k - base + HALO] * aval(j, k);
            }
            int d = i - j;
            if (d == 0)                 sre += (float)REGEPS;
            else if (d == 2 || d == -2) sre += sE[((i < j) ? i : j) - base + HALO];
            out[(size_t)i * DIM + j] = sre;
        }
    }
}

// ---------------- fallback path (unexpected out_size; fp64 reference math) ----
__device__ double g_aDiag[DIM];
__device__ double g_aOff1[DIM];
__device__ double g_dDiag[DIM];
__device__ double g_exp2[DIM];

__global__ void precompute_kernel(const float* __restrict__ s_real,
                                  const float* __restrict__ s_imag) {
    int m = blockIdx.x * blockDim.x + threadIdx.x;
    if (m >= DIM) return;
    const double PI = 3.141592653589793238462643383279502884;
    double sr = (double)s_real[0], si = (double)s_imag[0];
    g_aDiag[m] = 1.0 + THETA * cos(2.0 * PI * (double)m / (double)DIM);
    g_aOff1[m] = (m < DIM - 1) ? THETA * sin(PI * (2.0 * (double)m + 1.0) / (double)DIM) : 0.0;
    int n = m + 1;
    double ln_n = log((double)n);
    bool isp = (c_pmask[n >> 5] >> (n & 31)) & 1u;
    double dv = exp(-sr * ln_n) * cos(si * ln_n);
    if (isp) dv += THETA * ln_n * (PI * PI / 6.0);
    g_dDiag[m] = dv;
    g_exp2[m] = sqrt(sr * sr + si * si) * THETA * THETA * exp(-0.01 * (double)m);
}

__device__ __forceinline__ double AvalG(int x, int y) {
    if (y < 0 || y >= DIM) return 0.0;
    int d = x - y; d = d < 0 ? -d : d;
    if (d > 2) return 0.0;
    if (d == 0) return g_aDiag[x];
    if (d == 1) return g_aOff1[x < y ? x : y];
    return THETA * THETA * 0.8187307530779818586699355086383;
}

__global__ void fill_generic_f32(float* __restrict__ out, int n) {
    int idx = blockIdx.x * blockDim.x + threadIdx.x;
    if (idx >= n) return;
    int m = idx & (DIM * DIM - 1);
    int i = m >> 11, j = m & (DIM - 1);
    double sre = 0.0;
    #pragma unroll
    for (int kk = -2; kk <= 2; kk++) {
        int k = i + kk;
        if (k < 0 || k >= DIM) continue;
        sre += AvalG(i, k) * g_dDiag[k] * AvalG(j, k);
    }
    int d = i - j;
    if (d == 0) sre += REGEPS;
    else if (d == 2 || d == -2) sre += g_exp2[(i < j) ? i : j];
    out[idx] = (float)sre;
}

extern "C" void kernel_launch(void* const* d_in, const int* in_sizes, int n_in,
                              void* d_out, int out_size) {
    const float* s_real = (const float*)d_in[0];
    const float* s_imag = (const float*)((n_in >= 2) ? d_in[1] : d_in[0]);

    const int NTOT = DIM * DIM;
    if (out_size == NTOT) {
        fused_kernel<<<DIM / ROWS_PER_CTA, NTHREADS>>>(s_real, s_imag, (float*)d_out);
    } else {
        precompute_kernel<<<(DIM + 255) / 256, 256>>>(s_real, s_imag);
        fill_generic_f32<<<(out_size + 255) / 256, 256>>>((float*)d_out, out_size);
    }
}